// round 17
// baseline (speedup 1.0000x reference)
#include <cuda_runtime.h>
#include <cuda_bf16.h>
#include <cstdint>

// PosEnc: out[b, t, c] = coef if (c odd and c < chns-2) else 0
// Shapes fixed: batch=32, nfrms=4096, chns=1024 -> 2^27 floats = 512 MiB stores.
//
// float4 view (2^25 vec4s): every float4 = (0,c,0,c) EXCEPT the last float4
// of each 1024-col row (cols 1020..1023) = (0,c,0,0). Row = 256 float4s.
//
// History: R4 grid-strided 16K CTAs: 76.4us (DRAM 81%). R9 coarse 2K CTAs:
// 81.8us (waves quantize badly). R10 CTA-contiguous 32KiB chunks: 74.2us
// (DRAM 82.9%) = best. R11 __stcs: neutral -> reverted to plain stores.
// R17 (retry of R12-R16): halve chunk to 16 KiB (32768 CTAs x 256 thr x 4
// STG.128). The wave of ~1184 resident CTAs then writes a ~18.5 MiB live
// footprint instead of ~37 MiB -> fewer concurrently-open DRAM pages, better
// row-buffer hit rate. Fine waves proven cheap (R4 vs R9); contiguous chunks
// proven good (R10).

static constexpr int      THREADS   = 256;
static constexpr int      ITERS     = 4;
static constexpr unsigned N4        = 1u << 25;                        // total float4s
static constexpr int      BLOCKS    = (int)(N4 / (THREADS * ITERS));   // 32768
static constexpr unsigned CHUNK     = THREADS * ITERS;                 // 1024 float4s / CTA

__global__ __launch_bounds__(THREADS)
void posenc_fill_kernel(const float* __restrict__ coef_p,
                        float4* __restrict__ out) {
    const float c = __ldg(coef_p);

    // CTA-contiguous chunk; thread t writes chunk_base + k*256 + t.
    // Global idx % 256 == t (chunk_base, k*256 are multiples of 256), so the
    // row-tail (zero last lane, cols 1022..1023) is exactly t == 255:
    // the select hoists out of the loop, body is pure STG.128.
    const bool is_tail = (threadIdx.x == 255u);
    const float4 v = make_float4(0.0f, c, 0.0f, is_tail ? 0.0f : c);

    const unsigned base = blockIdx.x * CHUNK + threadIdx.x;

#pragma unroll
    for (int k = 0; k < ITERS; ++k) {
        out[base + (unsigned)k * THREADS] = v;
    }
}

extern "C" void kernel_launch(void* const* d_in, const int* in_sizes, int n_in,
                              void* d_out, int out_size) {
    // Inputs (metadata order): batch_size, nfrms, chns, coef_param (float32[1]).
    const float* coef = (const float*)d_in[n_in - 1];
    posenc_fill_kernel<<<BLOCKS, THREADS>>>(coef, (float4*)d_out);
}